// round 8
// baseline (speedup 1.0000x reference)
#include <cuda_runtime.h>
#include <cuda_bf16.h>
#include <math.h>

#define EPS 1e-9f

static constexpr int BMAX = 1024;
static constexpr int DMAX = 512;
static constexpr int UMAX = 512;

// Scratch (device globals — no allocation allowed)
__device__ float2 g_LN [BMAX * DMAX];       // {log2|x+eps|, bitcast(neg ? 0xFFFFFFFF : 0)}
__device__ float4 g_PW4[DMAX * UMAX / 2];   // per u-pair: {p0, w0, p1, w1}
__device__ uint2  g_OM2[DMAX * UMAX / 2];   // per u-pair: odd(p)?0x80000000:0

// ---------------- Fused prepass (also inits out = bias) ----------------
__global__ void prep_kernel(const float* __restrict__ x,
                            const float* __restrict__ w,
                            const float* __restrict__ p,
                            const float* __restrict__ bias,
                            float* __restrict__ out,
                            int nLN, int nPW, int nOut, int U) {
    int i = blockIdx.x * blockDim.x + threadIdx.x;
    if (i < nLN) {
        float xe = x[i] + EPS;
        float2 v;
        v.x = log2f(fabsf(xe));
        v.y = __uint_as_float((xe < 0.f) ? 0xFFFFFFFFu : 0u);
        g_LN[i] = v;
    }
    if (i < nPW) {
        const int U2 = U >> 1;
        int d  = i / U2;
        int u  = (i - d * U2) * 2;
        int idx = d * U + u;
        float p0 = p[idx],     p1 = p[idx + 1];
        float w0 = w[idx],     w1 = w[idx + 1];
        g_PW4[i] = make_float4(p0, w0, p1, w1);
        uint2 m;
        m.x = (fmodf(p0, 2.f) != 0.f) ? 0x80000000u : 0u;
        m.y = (fmodf(p1, 2.f) != 0.f) ? 0x80000000u : 0u;
        g_OM2[i] = m;
    }
    if (i < nOut) out[i] = bias[i % U];
}

// ---------------- Main kernel (compile-time shapes) ----------------
// upt=2 (adjacent u-pair), TBT=8 b-rows, DC=2 d-chunk, DSPLIT=8 over D,
// atomicAdd into bias-initialized out. All strides compile-time immediates.
static constexpr int DC      = 2;
static constexpr int TBT     = 8;
static constexpr int THREADS = 128;
static constexpr int DSPLIT  = 8;

template <int D, int U>
__global__ __launch_bounds__(THREADS, 10)
void power_layer_kernel(float* __restrict__ out) {
    constexpr int U2 = U / 2;
    constexpr int nD = D / DSPLIT;

    const int up  = blockIdx.y * THREADS + threadIdx.x;   // u-pair index
    const int b0  = blockIdx.x * TBT;
    const int dlo = blockIdx.z * nD;

    const float4* __restrict__ pwp = g_PW4 + dlo * U2 + up;
    const uint2*  __restrict__ omp = g_OM2 + dlo * U2 + up;
    const float2* __restrict__ lnb = g_LN  + (size_t)b0 * D + dlo;

    float2 acc[TBT];
#pragma unroll
    for (int bb = 0; bb < TBT; bb++) acc[bb] = make_float2(0.f, 0.f);

#pragma unroll 4
    for (int dd = 0; dd < nD; dd += DC) {
        float4 pw[DC];
        uint2  om[DC];
#pragma unroll
        for (int j = 0; j < DC; j++) {
            pw[j] = pwp[j * U2];     // LDG.128, immediate offset
            om[j] = omp[j * U2];     // LDG.64,  immediate offset
        }
        pwp += DC * U2;
        omp += DC * U2;

#pragma unroll
        for (int bb = 0; bb < TBT; bb++) {
            // warp-uniform -> broadcast; float4 = 2 x {log2, negmask}
            const float4 lnv =
                *(const float4*)(lnb + bb * D + dd);   // immediate offsets

#pragma unroll
            for (int j = 0; j < DC; j++) {
                const float        lv = (j & 1) ? lnv.z : lnv.x;
                const unsigned int nm = __float_as_uint((j & 1) ? lnv.w : lnv.y);

                float e0 = pw[j].x * lv;
                float e1 = pw[j].z * lv;
                float v0, v1;
                asm("ex2.approx.f32 %0, %1;" : "=f"(v0) : "f"(e0));
                asm("ex2.approx.f32 %0, %1;" : "=f"(v1) : "f"(e1));
                v0 = __uint_as_float(__float_as_uint(v0) ^ (om[j].x & nm));
                v1 = __uint_as_float(__float_as_uint(v1) ^ (om[j].y & nm));
                acc[bb].x = fmaf(pw[j].y, v0, acc[bb].x);
                acc[bb].y = fmaf(pw[j].w, v1, acc[bb].y);
            }
        }
    }

    float* o = out + (size_t)b0 * U + 2 * up;
#pragma unroll
    for (int bb = 0; bb < TBT; bb++) {
        atomicAdd(o + bb * U,     acc[bb].x);
        atomicAdd(o + bb * U + 1, acc[bb].y);
    }
}

// ---------------- Generic fallback (only if shapes differ) ----------------
__global__ void fallback_kernel(const float* __restrict__ x,
                                const float* __restrict__ w,
                                const float* __restrict__ p,
                                const float* __restrict__ bias,
                                float* __restrict__ out,
                                int B, int D, int U) {
    int i = blockIdx.x * blockDim.x + threadIdx.x;
    if (i >= B * U) return;
    int b = i / U, u = i % U;
    float s = 0.f;
    for (int d = 0; d < D; d++) {
        float xe = x[b * D + d] + EPS;
        float pv = p[d * U + u];
        float ap = powf(fabsf(xe), pv);
        bool odd = (fmodf(pv, 2.f) != 0.f);
        float sv = (odd && xe < 0.f) ? -ap : ap;
        s += w[d * U + u] * sv;
    }
    out[i] = s + bias[u];
}

// ---------------- Launch ----------------
extern "C" void kernel_launch(void* const* d_in, const int* in_sizes, int n_in,
                              void* d_out, int out_size) {
    const float* x    = (const float*)d_in[0];
    const float* w    = (const float*)d_in[1];
    const float* p    = (const float*)d_in[2];
    const float* bias = (const float*)d_in[3];
    float* out        = (float*)d_out;

    const int U = in_sizes[3];            // 512
    const int D = in_sizes[1] / U;        // 512
    const int B = in_sizes[0] / D;        // 1024

    if (U == 512 && D == 512 && B == 1024) {
        const int nLN  = B * D;           // 524288
        const int nPW  = D * U / 2;       // 131072
        const int nOut = out_size;        // 524288
        int nmax = nLN > nPW ? nLN : nPW;
        if (nOut > nmax) nmax = nOut;
        prep_kernel<<<(nmax + 255) / 256, 256>>>(x, w, p, bias, out,
                                                 nLN, nPW, nOut, U);

        // grid: (B/TBT, U2/THREADS, DSPLIT) = (128, 2, 8) = 2048 blocks
        dim3 grid(B / TBT, (U / 2) / THREADS, DSPLIT);
        power_layer_kernel<512, 512><<<grid, THREADS>>>(out);
    } else {
        int n = B * U;
        fallback_kernel<<<(n + 255) / 256, 256>>>(x, w, p, bias, out, B, D, U);
    }
}

// round 9
// speedup vs baseline: 1.1175x; 1.1175x over previous
#include <cuda_runtime.h>
#include <cuda_bf16.h>
#include <math.h>

#define EPS 1e-9f

static constexpr int BMAX = 1024;
static constexpr int DMAX = 512;
static constexpr int UMAX = 512;

// Scratch (device globals — no allocation allowed)
__device__ float2 g_LN [BMAX * DMAX];       // {log2|x+eps|, bitcast(neg ? 0xFFFFFFFF : 0)}
__device__ float4 g_PW4[DMAX * UMAX / 2];   // per u-pair: {p0, w0, p1, w1}
__device__ uint2  g_OM2[DMAX * UMAX / 2];   // per u-pair: odd(p)?0x80000000:0

// ---------------- Fused prepass (also inits out = bias) ----------------
__global__ void prep_kernel(const float* __restrict__ x,
                            const float* __restrict__ w,
                            const float* __restrict__ p,
                            const float* __restrict__ bias,
                            float* __restrict__ out,
                            int nLN, int nPW, int nOut, int U) {
    int i = blockIdx.x * blockDim.x + threadIdx.x;
    if (i < nLN) {
        float xe = x[i] + EPS;
        float2 v;
        v.x = log2f(fabsf(xe));
        v.y = __uint_as_float((xe < 0.f) ? 0xFFFFFFFFu : 0u);
        g_LN[i] = v;
    }
    if (i < nPW) {
        const int U2 = U >> 1;
        int d  = i / U2;
        int u  = (i - d * U2) * 2;
        int idx = d * U + u;
        float p0 = p[idx],     p1 = p[idx + 1];
        float w0 = w[idx],     w1 = w[idx + 1];
        g_PW4[i] = make_float4(p0, w0, p1, w1);
        uint2 m;
        m.x = (fmodf(p0, 2.f) != 0.f) ? 0x80000000u : 0u;
        m.y = (fmodf(p1, 2.f) != 0.f) ? 0x80000000u : 0u;
        g_OM2[i] = m;
    }
    if (i < nOut) out[i] = bias[i % U];
}

// v ^= (om & nm) in ONE LOP3: f(a,b,c) = a ^ (b & c) -> 0xF0 ^ (0xCC & 0xAA) = 0x78
__device__ __forceinline__ float sign_apply(float v, unsigned om, unsigned nm) {
    unsigned r = __float_as_uint(v);
    asm("lop3.b32 %0, %0, %1, %2, 0x78;" : "+r"(r) : "r"(om), "r"(nm));
    return __uint_as_float(r);
}

// ---------------- Main kernel (compile-time shapes) ----------------
// upt=2, TBT=8 b-rows, DC=2 d-chunk, DSPLIT=16, 2-stage prefetch of pw/om,
// atomicAdd into bias-initialized out.
static constexpr int DC      = 2;
static constexpr int TBT     = 8;
static constexpr int THREADS = 128;
static constexpr int DSPLIT  = 16;

template <int D, int U>
__global__ __launch_bounds__(THREADS, 8)
void power_layer_kernel(float* __restrict__ out) {
    constexpr int U2 = U / 2;
    constexpr int nD = D / DSPLIT;          // 32

    const int up  = blockIdx.y * THREADS + threadIdx.x;   // u-pair index
    const int b0  = blockIdx.x * TBT;
    const int dlo = blockIdx.z * nD;

    const float4* __restrict__ pwp = g_PW4 + dlo * U2 + up;
    const uint2*  __restrict__ omp = g_OM2 + dlo * U2 + up;
    const float2* __restrict__ lnb = g_LN  + (size_t)b0 * D + dlo;

    float2 acc[TBT];
#pragma unroll
    for (int bb = 0; bb < TBT; bb++) acc[bb] = make_float2(0.f, 0.f);

    // ---- 2-stage software pipeline over d-chunks ----
    float4 pwA[DC];  uint2 omA[DC];
    float4 pwB[DC];  uint2 omB[DC];
#pragma unroll
    for (int j = 0; j < DC; j++) {          // prologue: chunk 0
        pwA[j] = pwp[j * U2];
        omA[j] = omp[j * U2];
    }

#pragma unroll 2
    for (int dd = 0; dd < nD; dd += DC) {
        // prefetch next chunk
        if (dd + DC < nD) {
#pragma unroll
            for (int j = 0; j < DC; j++) {
                pwB[j] = pwp[(dd + DC + j) * U2 - dd * U2 + dd * U2];  // = pwp[(dd+DC+j)*U2]
                omB[j] = omp[(dd + DC + j) * U2];
            }
        }

#pragma unroll
        for (int bb = 0; bb < TBT; bb++) {
            // warp-uniform -> broadcast; float4 = 2 x {log2, negmask}
            const float4 lnv = *(const float4*)(lnb + bb * D + dd);

#pragma unroll
            for (int j = 0; j < DC; j++) {
                const float    lv = (j & 1) ? lnv.z : lnv.x;
                const unsigned nm = __float_as_uint((j & 1) ? lnv.w : lnv.y);

                float e0 = pwA[j].x * lv;
                float e1 = pwA[j].z * lv;
                float v0, v1;
                asm("ex2.approx.f32 %0, %1;" : "=f"(v0) : "f"(e0));
                asm("ex2.approx.f32 %0, %1;" : "=f"(v1) : "f"(e1));
                v0 = sign_apply(v0, omA[j].x, nm);
                v1 = sign_apply(v1, omA[j].y, nm);
                acc[bb].x = fmaf(pwA[j].y, v0, acc[bb].x);
                acc[bb].y = fmaf(pwA[j].w, v1, acc[bb].y);
            }
        }

        // rotate buffers (register renames after unroll-by-2)
#pragma unroll
        for (int j = 0; j < DC; j++) { pwA[j] = pwB[j]; omA[j] = omB[j]; }
    }

    float* o = out + (size_t)b0 * U + 2 * up;
#pragma unroll
    for (int bb = 0; bb < TBT; bb++) {
        atomicAdd(o + bb * U,     acc[bb].x);
        atomicAdd(o + bb * U + 1, acc[bb].y);
    }
}

// ---------------- Generic fallback (only if shapes differ) ----------------
__global__ void fallback_kernel(const float* __restrict__ x,
                                const float* __restrict__ w,
                                const float* __restrict__ p,
                                const float* __restrict__ bias,
                                float* __restrict__ out,
                                int B, int D, int U) {
    int i = blockIdx.x * blockDim.x + threadIdx.x;
    if (i >= B * U) return;
    int b = i / U, u = i % U;
    float s = 0.f;
    for (int d = 0; d < D; d++) {
        float xe = x[b * D + d] + EPS;
        float pv = p[d * U + u];
        float ap = powf(fabsf(xe), pv);
        bool odd = (fmodf(pv, 2.f) != 0.f);
        float sv = (odd && xe < 0.f) ? -ap : ap;
        s += w[d * U + u] * sv;
    }
    out[i] = s + bias[u];
}

// ---------------- Launch ----------------
extern "C" void kernel_launch(void* const* d_in, const int* in_sizes, int n_in,
                              void* d_out, int out_size) {
    const float* x    = (const float*)d_in[0];
    const float* w    = (const float*)d_in[1];
    const float* p    = (const float*)d_in[2];
    const float* bias = (const float*)d_in[3];
    float* out        = (float*)d_out;

    const int U = in_sizes[3];            // 512
    const int D = in_sizes[1] / U;        // 512
    const int B = in_sizes[0] / D;        // 1024

    if (U == 512 && D == 512 && B == 1024) {
        const int nLN  = B * D;           // 524288
        const int nPW  = D * U / 2;       // 131072
        const int nOut = out_size;        // 524288
        int nmax = nLN > nPW ? nLN : nPW;
        if (nOut > nmax) nmax = nOut;
        prep_kernel<<<(nmax + 255) / 256, 256>>>(x, w, p, bias, out,
                                                 nLN, nPW, nOut, U);

        // grid: (B/TBT, U2/THREADS, DSPLIT) = (128, 2, 16) = 4096 blocks
        dim3 grid(B / TBT, (U / 2) / THREADS, DSPLIT);
        power_layer_kernel<512, 512><<<grid, THREADS>>>(out);
    } else {
        int n = B * U;
        fallback_kernel<<<(n + 255) / 256, 256>>>(x, w, p, bias, out, B, D, U);
    }
}